// round 16
// baseline (speedup 1.0000x reference)
#include <cuda_runtime.h>

// 14-qubit, 5-layer variational circuit, batch 2048. One CTA (512 threads)
// per batch element. State = lane-pair ull arrays Rp/Ip[8192] (128 KB smem);
// each ull packs the two amplitudes differing in canonical qubit 13 (f32x2
// lanes). 3 rounds/layer, 16 packs (32 amps)/thread:
//   A: q0-3 (pack) + q13 (lane, mixed); prev ring fused into the gather.
//   B: q4-7 (pack) + q8 (shfl t4), in place. A->B warp-local -> __syncwarp.
//   C: q9-12 (pack), in place.
// Round-internal software pipelining: the cross-group level (pack bit 3)
// runs first; each 8-pack half then finishes its gates and scatters
// immediately, overlapping scatter crossbar with the other half's FMA and
// halving the STS burst at each barrier.
// Storage map M(q)=q^((q>>5)&31); all LDS.64/STS.64 patterns conflict-free.
// Layer 0 closed form; measurement fused into layer 4's round C.

#define NQ 14
#define NL 5
#define NA 6
#define NT 512

typedef unsigned long long ull;

// ---------- packed f32x2 helpers ----------
__device__ __forceinline__ ull pk(float lo, float hi) {
    ull r; asm("mov.b64 %0, {%1, %2};" : "=l"(r) : "f"(lo), "f"(hi)); return r;
}
__device__ __forceinline__ void upk(ull v, float& lo, float& hi) {
    asm("mov.b64 {%0, %1}, %2;" : "=f"(lo), "=f"(hi) : "l"(v));
}
__device__ __forceinline__ ull f2mul(ull a, ull b) {
    ull d; asm("mul.rn.f32x2 %0, %1, %2;" : "=l"(d) : "l"(a), "l"(b)); return d;
}
__device__ __forceinline__ ull f2fma(ull a, ull b, ull c) {
    ull d; asm("fma.rn.f32x2 %0, %1, %2, %3;" : "=l"(d) : "l"(a), "l"(b), "l"(c)); return d;
}
__device__ __forceinline__ ull swpl(ull v) {
    float a, b; upk(v, a, b); return pk(b, a);
}

struct Gate  { ull ar, ai, br, bi, nai, nbr, nbi; };
struct GateM { ull nai_ai, ai_nai, br_nbr; };

__device__ __forceinline__ void apply2(const Gate& g, ull& a0r, ull& a0i,
                                       ull& a1r, ull& a1i) {
    ull n0r = f2fma(g.br,  a1r, f2fma(g.nbi, a1i, f2fma(g.nai, a0i, f2mul(g.ar,  a0r))));
    ull n0i = f2fma(g.bi,  a1r, f2fma(g.br,  a1i, f2fma(g.ai,  a0r, f2mul(g.ar,  a0i))));
    ull n1r = f2fma(g.ai,  a1i, f2fma(g.ar,  a1r, f2fma(g.nbi, a0i, f2mul(g.nbr, a0r))));
    ull n1i = f2fma(g.nai, a1r, f2fma(g.ar,  a1i, f2fma(g.bi,  a0r, f2mul(g.nbr, a0i))));
    a0r = n0r; a0i = n0i; a1r = n1r; a1i = n1i;
}

// Gate on the f32x2 lane bit (canonical qubit 13), one pack.
__device__ __forceinline__ void apply_mixed(const Gate& g, const GateM& gm,
                                            ull& Pr, ull& Pi) {
    const ull Qr = swpl(Pr), Qi = swpl(Pi);
    ull Nr = f2fma(g.nbi,     Qi, f2fma(gm.br_nbr, Qr, f2fma(gm.nai_ai, Pi, f2mul(g.ar,      Pr))));
    ull Ni = f2fma(gm.br_nbr, Qi, f2fma(g.bi,      Qr, f2fma(g.ar,      Pi, f2mul(gm.ai_nai, Pr))));
    Pr = Nr; Pi = Ni;
}

// Gate on a warp-lane bit via shfl_xor, over 8 packs starting at base ptr.
__device__ __forceinline__ void shfl_gate8(const Gate& g, int role, unsigned msk,
                                           ull* Pr, ull* Pi) {
    const ull mycr  = g.ar;
    const ull myci  = role ? g.nai : g.ai;
    const ull nmyci = role ? g.ai  : g.nai;
    const ull pcr   = role ? g.nbr : g.br;
    const ull pci   = g.bi;
    const ull npci  = g.nbi;
    #pragma unroll
    for (int c = 0; c < 8; ++c) {
        const ull pR = __shfl_xor_sync(0xffffffffu, Pr[c], msk);
        const ull pI = __shfl_xor_sync(0xffffffffu, Pi[c], msk);
        const ull nr = f2fma(npci, pI, f2fma(pcr, pR,
                       f2fma(nmyci, Pi[c], f2mul(mycr, Pr[c]))));
        const ull ni = f2fma(pci,  pR, f2fma(pcr, pI,
                       f2fma(myci,  Pr[c], f2mul(mycr, Pi[c]))));
        Pr[c] = nr; Pi[c] = ni;
    }
}

// gate level within an 8-pack half starting at `base` (bit in {1,2,4})
#define LEVELH(g, bit, base)                                                 \
    {                                                                        \
        _Pragma("unroll")                                                    \
        for (int n = 0; n < 4; ++n) {                                        \
            const int lo = (base) + (((n & ~((bit) - 1)) << 1) | (n & ((bit) - 1))); \
            apply2(g, Pr[lo], Pi[lo], Pr[lo | (bit)], Pi[lo | (bit)]);       \
        }                                                                    \
    }

// cross-half level (pack bit 8): pairs (n, n+8)
#define LEVEL8F(g)                                                           \
    {                                                                        \
        _Pragma("unroll")                                                    \
        for (int n = 0; n < 8; ++n)                                          \
            apply2(g, Pr[n], Pi[n], Pr[n + 8], Pi[n + 8]);                   \
    }

// ---------- GF(2)-linear index maps ----------
__device__ constexpr int ringf14(int x) {
    int y = x;
    y ^= y << 1; y ^= y << 2; y ^= y << 4; y ^= y << 8;
    y &= 0x3FFF;
    return (y & 0x3FFE) | (((y >> 13) ^ x) & 1);
}
__device__ constexpr int ringinv14(int d) {
    int m  = (d ^ (d << 1)) & 0x3FFC;
    int m0 = ((d >> 13) ^ d) & 1;
    int m1 = ((d >> 13) ^ (d >> 1) ^ d) & 1;
    return m | m0 | (m1 << 1);
}
__device__ constexpr int M13v(int q) { return q ^ ((q >> 5) & 0x1F); }
// compile-time per-pack offsets
__device__ constexpr int OAG(int c) { return M13v(ringinv14(c) & 0x1FFF); }
__device__ constexpr int OBo(int c) { return M13v(c << 4); }
__device__ constexpr int OCo(int c) { return M13v(c << 9); }
__device__ constexpr int PAR4(int c) { return (0x6996 >> c) & 1; }

__global__ void __launch_bounds__(NT, 1)
qcirc_kernel(const float* __restrict__ x,        // [B, 14]
             const float* __restrict__ iscale,   // [5, 28]
             const float* __restrict__ wts,      // [5, 28]
             const float* __restrict__ ascale,   // [6]
             const float* __restrict__ abias,    // [6]
             float* __restrict__ out)            // [B, 6]
{
    extern __shared__ float2 sm2[];              // [16384] = 128 KB
    float2* R2 = sm2;                            // [8192] re pairs (q13 lanes)
    float2* I2 = sm2 + 8192;                     // [8192] im pairs
    ull* Rp = reinterpret_cast<ull*>(R2);
    ull* Ip = reinterpret_cast<ull*>(I2);

    __shared__ Gate  s_g[NL][NQ];
    __shared__ GateM s_gm[NL];                   // qubit 13 per layer
    __shared__ float s_u0[NQ][4];
    __shared__ float s_red[NT / 32][NA];

    const int t = threadIdx.x;
    const int b = blockIdx.x;

    // ---- fused gate tables: U = RY(beta) RZ(gamma) RY(alpha) --------------
    if (t < NL * NQ) {
        const int l = t / NQ, i = t % NQ;
        const float xi = x[b * NQ + i];
        const float* isl = iscale + l * 2 * NQ;
        const float* wl  = wts    + l * 2 * NQ;
        const float alpha = isl[i] * xi;
        const float gamma = isl[NQ + i] * xi + wl[i];
        const float beta  = wl[NQ + i];
        float sa, ca, sg, cg, sb, cb;
        sincosf(0.5f * alpha, &sa, &ca);
        sincosf(0.5f * gamma, &sg, &cg);
        sincosf(0.5f * beta,  &sb, &cb);
        const float cc = cb * ca, ss = sb * sa;
        const float cs = cb * sa, sc = sb * ca;
        const float ar =  cg * (cc - ss);
        const float ai = -sg * (cc + ss);
        const float br = -cg * (cs + sc);
        const float bi =  sg * (cs - sc);
        Gate gg;
        gg.ar = pk(ar, ar);   gg.ai = pk(ai, ai);
        gg.br = pk(br, br);   gg.bi = pk(bi, bi);
        gg.nai = pk(-ai, -ai); gg.nbr = pk(-br, -br); gg.nbi = pk(-bi, -bi);
        s_g[l][i] = gg;
        if (i == 13) {
            GateM gm;
            gm.nai_ai = pk(-ai, ai);
            gm.ai_nai = pk(ai, -ai);
            gm.br_nbr = pk(br, -br);
            s_gm[l] = gm;
        }
        if (l == 0) {
            s_u0[i][0] = ar; s_u0[i][1] = ai; s_u0[i][2] = br; s_u0[i][3] = bi;
        }
    }
    __syncthreads();

    // ---- per-round thread layouts ------------------------------------------
    // A: t0->q5 t1->q6 t2->q7 t3->q8 t4->q4; packs q0-3; warp t5-8->q9-12
    const int LAv = ((t & 1) << 5)        | (((t >> 1) & 1) << 6)
                  | (((t >> 2) & 1) << 7) | (((t >> 3) & 1) << 8)
                  | (((t >> 4) & 1) << 4) | (((t >> 5) & 15) << 9);
    const int rAi  = ringinv14(LAv);
    const int gA   = M13v(rAi & 0x1FFF);
    const int selA = (rAi >> 13) & 1;            // = t8 (source lane)
    const int sA   = M13v(LAv);
    // B: t0-3->q0-3, t4->q8; packs q4-7; warp t5-8->q9-12
    const int LBv = (t & 15) | (((t >> 4) & 1) << 8) | (((t >> 5) & 15) << 9);
    const int bB  = M13v(LBv);
    // C: t0-3->q5-8, t4->q4, t5-8->q0-3; packs q9-12
    const int LCv = ((t & 15) << 5) | (((t >> 4) & 1) << 4) | ((t >> 5) & 15);
    const int bC  = M13v(LCv);
    const int rfC = ringf14(LCv);                // measurement signs
    const int roleB = (t >> 4) & 1;              // q8 shfl role (mask 16)

    // ---- layer 0: pre-ring product state in round-C layout -----------------
    {
        const int Qmap[9] = {5, 6, 7, 8, 4, 0, 1, 2, 3};
        float Pr0 = 1.0f, Pi0 = 0.0f;
        #pragma unroll
        for (int j = 0; j < 9; ++j) {
            const int q = Qmap[j];
            const int bq = (t >> j) & 1;
            const float fr = bq ? -s_u0[q][2] : s_u0[q][0];
            const float fi = bq ?  s_u0[q][3] : s_u0[q][1];
            const float nr = Pr0 * fr - Pi0 * fi;
            Pi0 = Pr0 * fi + Pi0 * fr;
            Pr0 = nr;
        }
        float cr[16], ci[16];
        cr[0] = Pr0; ci[0] = Pi0;
        #pragma unroll
        for (int e = 0; e < 4; ++e) {            // pack bit e -> qubit 9+e
            const int q = 9 + e;
            const float a0r = s_u0[q][0], a0i = s_u0[q][1];
            const float f1r = -s_u0[q][2], f1i = s_u0[q][3];
            #pragma unroll
            for (int c = 0; c < (1 << e); ++c) {
                const float tr = cr[c], ti = ci[c];
                cr[c] = tr * a0r - ti * a0i;
                ci[c] = tr * a0i + ti * a0r;
                cr[c | (1 << e)] = tr * f1r - ti * f1i;
                ci[c | (1 << e)] = tr * f1i + ti * f1r;
            }
        }
        const float g0r = s_u0[13][0], g0i = s_u0[13][1];   // q13 lane factors
        const float g1r = -s_u0[13][2], g1i = s_u0[13][3];
        #pragma unroll
        for (int c = 0; c < 16; ++c) {
            const int a = bC ^ OCo(c);
            Rp[a] = pk(cr[c] * g0r - ci[c] * g0i, cr[c] * g1r - ci[c] * g1i);
            Ip[a] = pk(cr[c] * g0i + ci[c] * g0r, cr[c] * g1i + ci[c] * g1r);
        }
    }
    __syncthreads();

    float accS = 0.0f, acc0 = 0.0f;
    ull Pr[16], Pi[16];
    #pragma unroll 1
    for (int l = 1; l < NL; ++l) {
        // ===== round A: q0-3 (pack) + q13 (lane); prev ring fused ==========
        // source lane for the lane-0 target = selA; partner at address^3.
        if (selA == 0) {
            #pragma unroll
            for (int c = 0; c < 16; ++c) {
                const int a = gA ^ OAG(c);
                const float2 r0 = R2[a], r1 = R2[a ^ 3];
                const float2 i0 = I2[a], i1 = I2[a ^ 3];
                Pr[c] = pk(r0.x, r1.y);
                Pi[c] = pk(i0.x, i1.y);
            }
        } else {
            #pragma unroll
            for (int c = 0; c < 16; ++c) {
                const int a = gA ^ OAG(c);
                const float2 r0 = R2[a], r1 = R2[a ^ 3];
                const float2 i0 = I2[a], i1 = I2[a ^ 3];
                Pr[c] = pk(r0.y, r1.x);
                Pi[c] = pk(i0.y, i1.x);
            }
        }
        // cross-half level first: consumes ALL packs -> arrive immediately
        LEVEL8F(s_g[l][3])
        asm volatile("bar.arrive 1, %0;" :: "n"(2 * NT) : "memory");
        // half 0 finishes its gates during the barrier window
        LEVELH(s_g[l][0], 1, 0)
        LEVELH(s_g[l][1], 2, 0)
        LEVELH(s_g[l][2], 4, 0)
        {
            const Gate g = s_g[l][13];
            const GateM gm = s_gm[l];
            #pragma unroll
            for (int c = 0; c < 8; ++c) apply_mixed(g, gm, Pr[c], Pi[c]);
        }
        asm volatile("bar.sync 1, %0;" :: "n"(2 * NT) : "memory");
        #pragma unroll
        for (int c = 0; c < 8; ++c) {
            const int a = sA ^ c;
            Rp[a] = Pr[c]; Ip[a] = Pi[c];
        }
        // half 1 gates overlap other warps' scatters
        LEVELH(s_g[l][0], 1, 8)
        LEVELH(s_g[l][1], 2, 8)
        LEVELH(s_g[l][2], 4, 8)
        {
            const Gate g = s_g[l][13];
            const GateM gm = s_gm[l];
            #pragma unroll
            for (int c = 8; c < 16; ++c) apply_mixed(g, gm, Pr[c], Pi[c]);
        }
        #pragma unroll
        for (int c = 8; c < 16; ++c) {
            const int a = sA ^ c;
            Rp[a] = Pr[c]; Ip[a] = Pi[c];
        }
        __syncwarp();   // A->B exchanges data only within the warp (q9-12)

        // ===== round B: q4-7 (pack) + q8 (shfl t4), in place ===============
        #pragma unroll
        for (int c = 0; c < 16; ++c) {
            const int a = bB ^ OBo(c);
            Pr[c] = Rp[a]; Pi[c] = Ip[a];
        }
        LEVEL8F(s_g[l][7])
        LEVELH(s_g[l][4], 1, 0)
        LEVELH(s_g[l][5], 2, 0)
        LEVELH(s_g[l][6], 4, 0)
        shfl_gate8(s_g[l][8], roleB, 16, Pr, Pi);
        #pragma unroll
        for (int c = 0; c < 8; ++c) {
            const int a = bB ^ OBo(c);
            Rp[a] = Pr[c]; Ip[a] = Pi[c];
        }
        LEVELH(s_g[l][4], 1, 8)
        LEVELH(s_g[l][5], 2, 8)
        LEVELH(s_g[l][6], 4, 8)
        shfl_gate8(s_g[l][8], roleB, 16, Pr + 8, Pi + 8);
        #pragma unroll
        for (int c = 8; c < 16; ++c) {
            const int a = bB ^ OBo(c);
            Rp[a] = Pr[c]; Ip[a] = Pi[c];
        }
        __syncthreads();

        // ===== round C: q9-12 (pack), in place =============================
        #pragma unroll
        for (int c = 0; c < 16; ++c) {
            const int a = bC ^ OCo(c);
            Pr[c] = Rp[a]; Pi[c] = Ip[a];
        }
        LEVEL8F(s_g[l][12])
        LEVELH(s_g[l][9],  1, 0)
        LEVELH(s_g[l][10], 2, 0)
        LEVELH(s_g[l][11], 4, 0)
        if (l < NL - 1) {
            #pragma unroll
            for (int c = 0; c < 8; ++c) {
                const int a = bC ^ OCo(c);
                Rp[a] = Pr[c]; Ip[a] = Pi[c];
            }
            LEVELH(s_g[l][9],  1, 8)
            LEVELH(s_g[l][10], 2, 8)
            LEVELH(s_g[l][11], 4, 8)
            #pragma unroll
            for (int c = 8; c < 16; ++c) {
                const int a = bC ^ OCo(c);
                Rp[a] = Pr[c]; Ip[a] = Pi[c];
            }
            __syncthreads();
        } else {
            // ---- measurement fused with the final (owed) ring ------------
            // f = ringf(d): f1..f5 thread-constant (bits of rfC); f0 flips
            // with pack parity PAR4(c) and with the f32x2 lane (^0x2001).
            const int D0t = rfC & 1;
            #pragma unroll
            for (int c = 0; c < 8; ++c) {
                const ull Pp = f2fma(Pi[c], Pi[c], f2mul(Pr[c], Pr[c]));
                float p0, p1;
                upk(Pp, p0, p1);
                accS += p0 + p1;
                const float d = p0 - p1;
                acc0 += ((D0t ^ PAR4(c)) & 1) ? -d : d;
            }
            LEVELH(s_g[l][9],  1, 8)
            LEVELH(s_g[l][10], 2, 8)
            LEVELH(s_g[l][11], 4, 8)
            #pragma unroll
            for (int c = 8; c < 16; ++c) {
                const ull Pp = f2fma(Pi[c], Pi[c], f2mul(Pr[c], Pr[c]));
                float p0, p1;
                upk(Pp, p0, p1);
                accS += p0 + p1;
                const float d = p0 - p1;
                acc0 += ((D0t ^ PAR4(c)) & 1) ? -d : d;
            }
        }
    }

    // ---- per-thread signs, then block reduction of <Z_a> ------------------
    float acc[NA];
    acc[0] = acc0;
    #pragma unroll
    for (int a = 1; a < NA; ++a)
        acc[a] = ((rfC >> a) & 1) ? -accS : accS;

    #pragma unroll
    for (int a = 0; a < NA; ++a) {
        #pragma unroll
        for (int off = 16; off; off >>= 1)
            acc[a] += __shfl_xor_sync(0xffffffffu, acc[a], off);
    }
    const int lane = t & 31, warp = t >> 5;
    if (lane == 0) {
        #pragma unroll
        for (int a = 0; a < NA; ++a) s_red[warp][a] = acc[a];
    }
    __syncthreads();
    if (t < NA) {
        float s = 0.0f;
        #pragma unroll
        for (int w = 0; w < NT / 32; ++w) s += s_red[w][t];
        out[b * NA + t] = s * ascale[t] + abias[t];
    }
}

extern "C" void kernel_launch(void* const* d_in, const int* in_sizes, int n_in,
                              void* d_out, int out_size) {
    const float* x      = (const float*)d_in[0];
    const float* iscale = (const float*)d_in[1];
    const float* wts    = (const float*)d_in[2];
    const float* ascale = (const float*)d_in[3];
    const float* abias  = (const float*)d_in[4];
    float* out = (float*)d_out;
    const int B = in_sizes[0] / NQ;

    const size_t shmem = (size_t)16384 * sizeof(float2);   // 128 KB
    cudaFuncSetAttribute(qcirc_kernel,
                         cudaFuncAttributeMaxDynamicSharedMemorySize,
                         (int)shmem);
    qcirc_kernel<<<B, NT, shmem>>>(x, iscale, wts, ascale, abias, out);
}

// round 17
// speedup vs baseline: 1.0396x; 1.0396x over previous
#include <cuda_runtime.h>

// 14-qubit, 5-layer variational circuit, batch 2048. One CTA (512 threads)
// per batch element. State = lane-pair ull arrays Rp/Ip[8192] (128 KB smem);
// each ull packs the two amplitudes differing in canonical qubit 13 (f32x2
// lanes). 3 rounds/layer, 16 packs (32 amps)/thread:
//   A: q0-3 (pack) + q13 (lane, mixed); prev ring fused into the gather.
//      Pack pair (c, c^1) + lane partners share addresses {a, a^3}
//      (ringinv(e_q0) -> 3, ringinv(e_q13) -> 0x2003) -> 32 LDS.64 total.
//      Split barrier: bar.arrive after gather consumed, math, bar.sync.
//   B: q4-7 (pack) + q8 (shfl t4), in place. A->B warp-local -> __syncwarp.
//   C: q9-12 (pack), in place.
// Storage map M(q)=q^((q>>5)&31); all LDS.64/STS.64 patterns conflict-free.
// Layer 0 closed form; measurement fused into layer 4's round C.

#define NQ 14
#define NL 5
#define NA 6
#define NT 512

typedef unsigned long long ull;

// ---------- packed f32x2 helpers ----------
__device__ __forceinline__ ull pk(float lo, float hi) {
    ull r; asm("mov.b64 %0, {%1, %2};" : "=l"(r) : "f"(lo), "f"(hi)); return r;
}
__device__ __forceinline__ void upk(ull v, float& lo, float& hi) {
    asm("mov.b64 {%0, %1}, %2;" : "=f"(lo), "=f"(hi) : "l"(v));
}
__device__ __forceinline__ ull f2mul(ull a, ull b) {
    ull d; asm("mul.rn.f32x2 %0, %1, %2;" : "=l"(d) : "l"(a), "l"(b)); return d;
}
__device__ __forceinline__ ull f2fma(ull a, ull b, ull c) {
    ull d; asm("fma.rn.f32x2 %0, %1, %2, %3;" : "=l"(d) : "l"(a), "l"(b), "l"(c)); return d;
}
__device__ __forceinline__ ull swpl(ull v) {
    float a, b; upk(v, a, b); return pk(b, a);
}

struct Gate  { ull ar, ai, br, bi, nai, nbr, nbi; };
struct GateM { ull nai_ai, ai_nai, br_nbr; };

__device__ __forceinline__ void apply2(const Gate& g, ull& a0r, ull& a0i,
                                       ull& a1r, ull& a1i) {
    ull n0r = f2fma(g.br,  a1r, f2fma(g.nbi, a1i, f2fma(g.nai, a0i, f2mul(g.ar,  a0r))));
    ull n0i = f2fma(g.bi,  a1r, f2fma(g.br,  a1i, f2fma(g.ai,  a0r, f2mul(g.ar,  a0i))));
    ull n1r = f2fma(g.ai,  a1i, f2fma(g.ar,  a1r, f2fma(g.nbi, a0i, f2mul(g.nbr, a0r))));
    ull n1i = f2fma(g.nai, a1r, f2fma(g.ar,  a1i, f2fma(g.bi,  a0r, f2mul(g.nbr, a0i))));
    a0r = n0r; a0i = n0i; a1r = n1r; a1i = n1i;
}

// Gate on the f32x2 lane bit (canonical qubit 13), one pack.
__device__ __forceinline__ void apply_mixed(const Gate& g, const GateM& gm,
                                            ull& Pr, ull& Pi) {
    const ull Qr = swpl(Pr), Qi = swpl(Pi);
    ull Nr = f2fma(g.nbi,     Qi, f2fma(gm.br_nbr, Qr, f2fma(gm.nai_ai, Pi, f2mul(g.ar,      Pr))));
    ull Ni = f2fma(gm.br_nbr, Qi, f2fma(g.bi,      Qr, f2fma(g.ar,      Pi, f2mul(gm.ai_nai, Pr))));
    Pr = Nr; Pi = Ni;
}

// Gate on a warp-lane bit via shfl_xor (both f32x2 lanes at once), 16 packs.
__device__ __forceinline__ void shfl_gate16(const Gate& g, int role, unsigned msk,
                                            ull* Pr, ull* Pi) {
    const ull mycr  = g.ar;
    const ull myci  = role ? g.nai : g.ai;
    const ull nmyci = role ? g.ai  : g.nai;
    const ull pcr   = role ? g.nbr : g.br;
    const ull pci   = g.bi;
    const ull npci  = g.nbi;
    #pragma unroll
    for (int c = 0; c < 16; ++c) {
        const ull pR = __shfl_xor_sync(0xffffffffu, Pr[c], msk);
        const ull pI = __shfl_xor_sync(0xffffffffu, Pi[c], msk);
        const ull nr = f2fma(npci, pI, f2fma(pcr, pR,
                       f2fma(nmyci, Pi[c], f2mul(mycr, Pr[c]))));
        const ull ni = f2fma(pci,  pR, f2fma(pcr, pI,
                       f2fma(myci,  Pr[c], f2mul(mycr, Pi[c]))));
        Pr[c] = nr; Pi[c] = ni;
    }
}

// one gate level over 16 packs (pairs differ in pack bit `bit`)
#define LEVEL(g, bit)                                                        \
    {                                                                        \
        _Pragma("unroll")                                                    \
        for (int n = 0; n < 8; ++n) {                                        \
            const int lo = ((n & ~((bit) - 1)) << 1) | (n & ((bit) - 1));    \
            apply2(g, Pr[lo], Pi[lo], Pr[lo | (bit)], Pi[lo | (bit)]);       \
        }                                                                    \
    }

// ---------- GF(2)-linear index maps ----------
__device__ constexpr int ringf14(int x) {
    int y = x;
    y ^= y << 1; y ^= y << 2; y ^= y << 4; y ^= y << 8;
    y &= 0x3FFF;
    return (y & 0x3FFE) | (((y >> 13) ^ x) & 1);
}
__device__ constexpr int ringinv14(int d) {
    int m  = (d ^ (d << 1)) & 0x3FFC;
    int m0 = ((d >> 13) ^ d) & 1;
    int m1 = ((d >> 13) ^ (d >> 1) ^ d) & 1;
    return m | m0 | (m1 << 1);
}
__device__ constexpr int M13v(int q) { return q ^ ((q >> 5) & 0x1F); }
// compile-time per-pack offsets
__device__ constexpr int OAG(int c) { return M13v(ringinv14(c) & 0x1FFF); }
__device__ constexpr int OBo(int c) { return M13v(c << 4); }
__device__ constexpr int OCo(int c) { return M13v(c << 9); }
__device__ constexpr int PAR4(int c) { return (0x6996 >> c) & 1; }

__global__ void __launch_bounds__(NT, 1)
qcirc_kernel(const float* __restrict__ x,        // [B, 14]
             const float* __restrict__ iscale,   // [5, 28]
             const float* __restrict__ wts,      // [5, 28]
             const float* __restrict__ ascale,   // [6]
             const float* __restrict__ abias,    // [6]
             float* __restrict__ out)            // [B, 6]
{
    extern __shared__ float2 sm2[];              // [16384] = 128 KB
    float2* R2 = sm2;                            // [8192] re pairs (q13 lanes)
    float2* I2 = sm2 + 8192;                     // [8192] im pairs
    ull* Rp = reinterpret_cast<ull*>(R2);
    ull* Ip = reinterpret_cast<ull*>(I2);

    __shared__ Gate  s_g[NL][NQ];
    __shared__ GateM s_gm[NL];                   // qubit 13 per layer
    __shared__ float s_u0[NQ][4];
    __shared__ float s_red[NT / 32][NA];

    const int t = threadIdx.x;
    const int b = blockIdx.x;

    // ---- fused gate tables: U = RY(beta) RZ(gamma) RY(alpha) --------------
    if (t < NL * NQ) {
        const int l = t / NQ, i = t % NQ;
        const float xi = x[b * NQ + i];
        const float* isl = iscale + l * 2 * NQ;
        const float* wl  = wts    + l * 2 * NQ;
        const float alpha = isl[i] * xi;
        const float gamma = isl[NQ + i] * xi + wl[i];
        const float beta  = wl[NQ + i];
        float sa, ca, sg, cg, sb, cb;
        sincosf(0.5f * alpha, &sa, &ca);
        sincosf(0.5f * gamma, &sg, &cg);
        sincosf(0.5f * beta,  &sb, &cb);
        const float cc = cb * ca, ss = sb * sa;
        const float cs = cb * sa, sc = sb * ca;
        const float ar =  cg * (cc - ss);
        const float ai = -sg * (cc + ss);
        const float br = -cg * (cs + sc);
        const float bi =  sg * (cs - sc);
        Gate gg;
        gg.ar = pk(ar, ar);   gg.ai = pk(ai, ai);
        gg.br = pk(br, br);   gg.bi = pk(bi, bi);
        gg.nai = pk(-ai, -ai); gg.nbr = pk(-br, -br); gg.nbi = pk(-bi, -bi);
        s_g[l][i] = gg;
        if (i == 13) {
            GateM gm;
            gm.nai_ai = pk(-ai, ai);
            gm.ai_nai = pk(ai, -ai);
            gm.br_nbr = pk(br, -br);
            s_gm[l] = gm;
        }
        if (l == 0) {
            s_u0[i][0] = ar; s_u0[i][1] = ai; s_u0[i][2] = br; s_u0[i][3] = bi;
        }
    }
    __syncthreads();

    // ---- per-round thread layouts ------------------------------------------
    // A: t0->q5 t1->q6 t2->q7 t3->q8 t4->q4; packs q0-3; warp t5-8->q9-12
    const int LAv = ((t & 1) << 5)        | (((t >> 1) & 1) << 6)
                  | (((t >> 2) & 1) << 7) | (((t >> 3) & 1) << 8)
                  | (((t >> 4) & 1) << 4) | (((t >> 5) & 15) << 9);
    const int rAi  = ringinv14(LAv);
    const int gA   = M13v(rAi & 0x1FFF);
    const int selA = (rAi >> 13) & 1;            // = t8 (source lane)
    const int sA   = M13v(LAv);
    // B: t0-3->q0-3, t4->q8; packs q4-7; warp t5-8->q9-12
    const int LBv = (t & 15) | (((t >> 4) & 1) << 8) | (((t >> 5) & 15) << 9);
    const int bB  = M13v(LBv);
    // C: t0-3->q5-8, t4->q4, t5-8->q0-3; packs q9-12
    const int LCv = ((t & 15) << 5) | (((t >> 4) & 1) << 4) | ((t >> 5) & 15);
    const int bC  = M13v(LCv);
    const int rfC = ringf14(LCv);                // measurement signs
    const int roleB = (t >> 4) & 1;              // q8 shfl role (mask 16)

    // ---- layer 0: pre-ring product state in round-C layout -----------------
    {
        const int Qmap[9] = {5, 6, 7, 8, 4, 0, 1, 2, 3};
        float Pr0 = 1.0f, Pi0 = 0.0f;
        #pragma unroll
        for (int j = 0; j < 9; ++j) {
            const int q = Qmap[j];
            const int bq = (t >> j) & 1;
            const float fr = bq ? -s_u0[q][2] : s_u0[q][0];
            const float fi = bq ?  s_u0[q][3] : s_u0[q][1];
            const float nr = Pr0 * fr - Pi0 * fi;
            Pi0 = Pr0 * fi + Pi0 * fr;
            Pr0 = nr;
        }
        float cr[16], ci[16];
        cr[0] = Pr0; ci[0] = Pi0;
        #pragma unroll
        for (int e = 0; e < 4; ++e) {            // pack bit e -> qubit 9+e
            const int q = 9 + e;
            const float a0r = s_u0[q][0], a0i = s_u0[q][1];
            const float f1r = -s_u0[q][2], f1i = s_u0[q][3];
            #pragma unroll
            for (int c = 0; c < (1 << e); ++c) {
                const float tr = cr[c], ti = ci[c];
                cr[c] = tr * a0r - ti * a0i;
                ci[c] = tr * a0i + ti * a0r;
                cr[c | (1 << e)] = tr * f1r - ti * f1i;
                ci[c | (1 << e)] = tr * f1i + ti * f1r;
            }
        }
        const float g0r = s_u0[13][0], g0i = s_u0[13][1];   // q13 lane factors
        const float g1r = -s_u0[13][2], g1i = s_u0[13][3];
        #pragma unroll
        for (int c = 0; c < 16; ++c) {
            const int a = bC ^ OCo(c);
            Rp[a] = pk(cr[c] * g0r - ci[c] * g0i, cr[c] * g1r - ci[c] * g1i);
            Ip[a] = pk(cr[c] * g0i + ci[c] * g0r, cr[c] * g1i + ci[c] * g1r);
        }
    }
    __syncthreads();

    float accS = 0.0f, acc0 = 0.0f;
    ull Pr[16], Pi[16];
    #pragma unroll 1
    for (int l = 1; l < NL; ++l) {
        // ===== round A: q0-3 (pack) + q13 (lane); prev ring fused ==========
        // Pack pair (2p, 2p+1) + both lanes share addresses {a, a^3}:
        // ringinv(e_q0)->0x3, ringinv(e_q13)->0x2003 (addr ^3, lane flip).
        if (selA == 0) {
            #pragma unroll
            for (int p = 0; p < 8; ++p) {
                const int a = gA ^ OAG(2 * p);
                const float2 r0 = R2[a], r1 = R2[a ^ 3];
                const float2 i0 = I2[a], i1 = I2[a ^ 3];
                Pr[2*p]   = pk(r0.x, r1.y);  Pi[2*p]   = pk(i0.x, i1.y);
                Pr[2*p+1] = pk(r1.x, r0.y);  Pi[2*p+1] = pk(i1.x, i0.y);
            }
        } else {
            #pragma unroll
            for (int p = 0; p < 8; ++p) {
                const int a = gA ^ OAG(2 * p);
                const float2 r0 = R2[a], r1 = R2[a ^ 3];
                const float2 i0 = I2[a], i1 = I2[a ^ 3];
                Pr[2*p]   = pk(r0.y, r1.x);  Pi[2*p]   = pk(i0.y, i1.x);
                Pr[2*p+1] = pk(r1.y, r0.x);  Pi[2*p+1] = pk(i1.y, i0.x);
            }
        }
        // first level consumes ALL loaded packs -> loads complete before arrive
        LEVEL(s_g[l][0], 1)
        asm volatile("bar.arrive 1, %0;" :: "n"(2 * NT) : "memory");
        LEVEL(s_g[l][1], 2)
        LEVEL(s_g[l][2], 4)
        LEVEL(s_g[l][3], 8)
        {
            const Gate g = s_g[l][13];
            const GateM gm = s_gm[l];
            #pragma unroll
            for (int c = 0; c < 16; ++c) apply_mixed(g, gm, Pr[c], Pi[c]);
        }
        // wait until every thread's gather is consumed, then scatter
        asm volatile("bar.sync 1, %0;" :: "n"(2 * NT) : "memory");
        #pragma unroll
        for (int c = 0; c < 16; ++c) {
            const int a = sA ^ c;                 // M(c)=c for c<16
            Rp[a] = Pr[c]; Ip[a] = Pi[c];
        }
        __syncwarp();   // A->B exchanges data only within the warp (q9-12)

        // ===== round B: q4-7 (pack) + q8 (shfl t4), in place ===============
        #pragma unroll
        for (int c = 0; c < 16; ++c) {
            const int a = bB ^ OBo(c);
            Pr[c] = Rp[a]; Pi[c] = Ip[a];
        }
        LEVEL(s_g[l][4], 1)
        LEVEL(s_g[l][5], 2)
        LEVEL(s_g[l][6], 4)
        LEVEL(s_g[l][7], 8)
        shfl_gate16(s_g[l][8], roleB, 16, Pr, Pi);
        #pragma unroll
        for (int c = 0; c < 16; ++c) {
            const int a = bB ^ OBo(c);
            Rp[a] = Pr[c]; Ip[a] = Pi[c];
        }
        __syncthreads();

        // ===== round C: q9-12 (pack), in place =============================
        #pragma unroll
        for (int c = 0; c < 16; ++c) {
            const int a = bC ^ OCo(c);
            Pr[c] = Rp[a]; Pi[c] = Ip[a];
        }
        LEVEL(s_g[l][9],  1)
        LEVEL(s_g[l][10], 2)
        LEVEL(s_g[l][11], 4)
        LEVEL(s_g[l][12], 8)
        if (l < NL - 1) {
            #pragma unroll
            for (int c = 0; c < 16; ++c) {
                const int a = bC ^ OCo(c);
                Rp[a] = Pr[c]; Ip[a] = Pi[c];
            }
            __syncthreads();
        } else {
            // ---- measurement fused with the final (owed) ring ------------
            // f = ringf(d): f1..f5 thread-constant (bits of rfC); f0 flips
            // with pack parity PAR4(c) and with the f32x2 lane (^0x2001).
            const int D0t = rfC & 1;
            #pragma unroll
            for (int c = 0; c < 16; ++c) {
                const ull Pp = f2fma(Pi[c], Pi[c], f2mul(Pr[c], Pr[c]));
                float p0, p1;
                upk(Pp, p0, p1);
                accS += p0 + p1;
                const float d = p0 - p1;
                acc0 += ((D0t ^ PAR4(c)) & 1) ? -d : d;
            }
        }
    }

    // ---- per-thread signs, then block reduction of <Z_a> ------------------
    float acc[NA];
    acc[0] = acc0;
    #pragma unroll
    for (int a = 1; a < NA; ++a)
        acc[a] = ((rfC >> a) & 1) ? -accS : accS;

    #pragma unroll
    for (int a = 0; a < NA; ++a) {
        #pragma unroll
        for (int off = 16; off; off >>= 1)
            acc[a] += __shfl_xor_sync(0xffffffffu, acc[a], off);
    }
    const int lane = t & 31, warp = t >> 5;
    if (lane == 0) {
        #pragma unroll
        for (int a = 0; a < NA; ++a) s_red[warp][a] = acc[a];
    }
    __syncthreads();
    if (t < NA) {
        float s = 0.0f;
        #pragma unroll
        for (int w = 0; w < NT / 32; ++w) s += s_red[w][t];
        out[b * NA + t] = s * ascale[t] + abias[t];
    }
}

extern "C" void kernel_launch(void* const* d_in, const int* in_sizes, int n_in,
                              void* d_out, int out_size) {
    const float* x      = (const float*)d_in[0];
    const float* iscale = (const float*)d_in[1];
    const float* wts    = (const float*)d_in[2];
    const float* ascale = (const float*)d_in[3];
    const float* abias  = (const float*)d_in[4];
    float* out = (float*)d_out;
    const int B = in_sizes[0] / NQ;

    const size_t shmem = (size_t)16384 * sizeof(float2);   // 128 KB
    cudaFuncSetAttribute(qcirc_kernel,
                         cudaFuncAttributeMaxDynamicSharedMemorySize,
                         (int)shmem);
    qcirc_kernel<<<B, NT, shmem>>>(x, iscale, wts, ascale, abias, out);
}